// round 13
// baseline (speedup 1.0000x reference)
#include <cuda_runtime.h>

// LSTM_824633721296: 2-layer LSTM (B=1024, T=512, I=8, H=64) + FC(64->10), fp32.
// Persistent per-CTA design: 148 CTAs x 256 threads (one per SM), 6-7 batch
// elements per CTA (load-balanced), weights register-resident per gate-row
// thread, packed f32x2 FMA mainloop. Layer-private gate buffers -> 3 barriers/step.

#define Bt    1024
#define Tt    512
#define NI    8
#define Hh    64
#define Gg    256   // 4*H
#define NO    10
#define NBMAX 7     // max batches per CTA
#define NT    256   // threads per CTA
#define NCTA  148
#define EXTRA (Bt - NCTA * 6)   // 136 CTAs carry a 7th batch

typedef unsigned long long ull;

__device__ __forceinline__ void fma2(ull &d, ull a, ull b) {
    asm("fma.rn.f32x2 %0, %1, %2, %0;" : "+l"(d) : "l"(a), "l"(b));
}
__device__ __forceinline__ ull pack2(float lo, float hi) {
    ull r; asm("mov.b64 %0, {%1, %2};" : "=l"(r) : "f"(lo), "f"(hi)); return r;
}
__device__ __forceinline__ float hsum2(ull a) {
    float lo, hi; asm("mov.b64 {%0, %1}, %2;" : "=f"(lo), "=f"(hi) : "l"(a));
    return lo + hi;
}
__device__ __forceinline__ float sigf(float x) {
    float e = __expf(-x);
    return __fdividef(1.0f, 1.0f + e);
}
__device__ __forceinline__ float tanh_f(float x) {
    // tanh(x) = 1 - 2/(e^{2x}+1); saturates correctly for |x| large.
    float e = __expf(2.0f * x);
    return 1.0f - __fdividef(2.0f, e + 1.0f);
}

__global__ void __launch_bounds__(NT, 1) lstm_kernel(
    const float* __restrict__ x,
    const float* __restrict__ w_ih0, const float* __restrict__ w_hh0,
    const float* __restrict__ b_ih0, const float* __restrict__ b_hh0,
    const float* __restrict__ w_ih1, const float* __restrict__ w_hh1,
    const float* __restrict__ b_ih1, const float* __restrict__ b_hh1,
    const float* __restrict__ w_fc,  const float* __restrict__ b_fc,
    float* __restrict__ out)
{
    __shared__ __align__(16) float h0_sm[NBMAX][Hh];   // layer0 hidden [b][j]
    __shared__ __align__(16) float h1_sm[NBMAX][Hh];   // layer1 hidden
    __shared__ __align__(16) float g0_sm[Gg][9];       // layer0 gates (stride 9)
    __shared__ __align__(16) float g1_sm[Gg][9];       // layer1 gates (stride 9)
    __shared__ __align__(16) float x_sm[2][NBMAX][NI]; // double-buffered x_t

    const int tid = threadIdx.x;
    const int g   = tid;                         // gate row this thread owns
    const int cta = blockIdx.x;
    const int nb    = 6 + (cta < EXTRA ? 1 : 0);
    const int bbase = cta * 6 + (cta < EXTRA ? cta : EXTRA);
    const bool big  = (nb == NBMAX);

    // ---- Load this gate row's weights into registers, packed as j-pairs ----
    ull wh0[Hh/2], wx0[NI/2], wi1[Hh/2], wh1[Hh/2];
    {
        const ull* p = (const ull*)(w_hh0 + g * Hh);
        #pragma unroll
        for (int i = 0; i < Hh/2; i++) wh0[i] = p[i];
        p = (const ull*)(w_ih0 + g * NI);
        #pragma unroll
        for (int i = 0; i < NI/2; i++) wx0[i] = p[i];
        p = (const ull*)(w_ih1 + g * Hh);
        #pragma unroll
        for (int i = 0; i < Hh/2; i++) wi1[i] = p[i];
        p = (const ull*)(w_hh1 + g * Hh);
        #pragma unroll
        for (int i = 0; i < Hh/2; i++) wh1[i] = p[i];
    }
    const float bias0 = b_ih0[g] + b_hh0[g];
    const float bias1 = b_ih1[g] + b_hh1[g];

    // ---- Activation-role mapping: thread -> (hidden unit aj, batches ab0, ab1)
    const int aj  = tid & (Hh - 1);
    const int aq  = tid >> 6;              // 0..3
    const int ab0 = 2 * aq, ab1 = 2 * aq + 1;
    const bool has0 = (ab0 < nb), has1 = (ab1 < nb);
    float c0a = 0.f, c0b = 0.f;            // layer0 cell state
    float c1a = 0.f, c1b = 0.f;            // layer1 cell state

    // ---- Zero initial hidden states ----
    for (int i = tid; i < NBMAX * Hh; i += NT) {
        (&h0_sm[0][0])[i] = 0.f;
        (&h1_sm[0][0])[i] = 0.f;
    }
    // ---- Stage x_t for t=0 ----
    if (tid < 2 * nb) {
        int b = tid >> 1, half = tid & 1;
        float4 v = *(const float4*)(x + ((bbase + b) * Tt + 0) * NI + half * 4);
        *(float4*)&x_sm[0][b][half * 4] = v;
    }
    __syncthreads();

    float4 xpre = make_float4(0.f, 0.f, 0.f, 0.f);

    for (int t = 0; t < Tt; t++) {
        const int buf = t & 1;

        // Prefetch x_{t+1} (latency hidden under phase 1/3 compute)
        if (tid < 2 * nb) {
            int tn = (t + 1 < Tt) ? (t + 1) : t;
            int b = tid >> 1, half = tid & 1;
            xpre = *(const float4*)(x + ((bbase + b) * Tt + tn) * NI + half * 4);
        }

        // ---------- Phase 1: layer0 gates: bias0 + w_ih0.x_t + w_hh0.h0 ----------
        // (g0_sm WAR vs phase 2 of step t-1 is covered by B2,B3 of step t-1.)
        #pragma unroll
        for (int b = 0; b < NBMAX; b++) {
            if (b == 6 && !big) break;
            ull acc0 = pack2(bias0, 0.f);
            ull acc1 = pack2(0.f, 0.f);
            // x-terms first: independent FMAs cover the first h-LDS latency.
            const ulonglong2* xp = (const ulonglong2*)&x_sm[buf][b][0];
            {
                ulonglong2 xv0 = xp[0];
                ulonglong2 xv1 = xp[1];
                fma2(acc0, wx0[0], xv0.x);
                fma2(acc1, wx0[1], xv0.y);
                fma2(acc0, wx0[2], xv1.x);
                fma2(acc1, wx0[3], xv1.y);
            }
            const ulonglong2* hp = (const ulonglong2*)&h0_sm[b][0];
            #pragma unroll
            for (int k = 0; k < Hh/4; k++) {
                ulonglong2 hv = hp[k];
                fma2(acc0, wh0[2*k],     hv.x);
                fma2(acc1, wh0[2*k + 1], hv.y);
            }
            g0_sm[g][b] = hsum2(acc0) + hsum2(acc1);
        }
        __syncthreads();   // B1: g0 writes -> phase 2 reads

        // ---------- Phase 2: layer0 activations -> new h0 ----------
        if (has0) {
            float ia = g0_sm[aj      ][ab0];
            float fa = g0_sm[aj +  64][ab0];
            float ga = g0_sm[aj + 128][ab0];
            float oa = g0_sm[aj + 192][ab0];
            c0a = sigf(fa) * c0a + sigf(ia) * tanh_f(ga);
            h0_sm[ab0][aj] = sigf(oa) * tanh_f(c0a);
        }
        if (has1) {
            float ib = g0_sm[aj      ][ab1];
            float fb = g0_sm[aj +  64][ab1];
            float gb = g0_sm[aj + 128][ab1];
            float ob = g0_sm[aj + 192][ab1];
            c0b = sigf(fb) * c0b + sigf(ib) * tanh_f(gb);
            h0_sm[ab1][aj] = sigf(ob) * tanh_f(c0b);
        }
        __syncthreads();   // B2: h0 writes -> phase 3 reads

        // ---------- Phase 3: layer1 gates: bias1 + w_ih1.h0_new + w_hh1.h1 ----------
        // h0 and h1 loads interleaved: 2 independent LDS.128 per iteration.
        #pragma unroll
        for (int b = 0; b < NBMAX; b++) {
            if (b == 6 && !big) break;
            ull acc0 = pack2(bias1, 0.f);
            ull acc1 = pack2(0.f, 0.f);
            const ulonglong2* hp0 = (const ulonglong2*)&h0_sm[b][0];
            const ulonglong2* hp1 = (const ulonglong2*)&h1_sm[b][0];
            #pragma unroll
            for (int k = 0; k < Hh/4; k++) {
                ulonglong2 hv0 = hp0[k];
                ulonglong2 hv1 = hp1[k];
                fma2(acc0, wi1[2*k],     hv0.x);
                fma2(acc1, wi1[2*k + 1], hv0.y);
                fma2(acc0, wh1[2*k],     hv1.x);
                fma2(acc1, wh1[2*k + 1], hv1.y);
            }
            g1_sm[g][b] = hsum2(acc0) + hsum2(acc1);
        }
        // Park prefetched x into the other buffer (writer pre-B3; reader at
        // t+1 phase 1 is post-B3 for every thread).
        if (tid < 2 * nb) {
            int b = tid >> 1, half = tid & 1;
            *(float4*)&x_sm[buf ^ 1][b][half * 4] = xpre;
        }
        __syncthreads();   // B3: g1 writes -> phase 4 reads

        // ---------- Phase 4: layer1 activations -> new h1 ----------
        // No trailing barrier: next-step phase 1 touches only g0/h0/x, all of
        // whose hazards are separated by >=2 barriers; P4's h1 writes and g1
        // reads are ordered before next-step phase 3 by B1,B2 of step t+1.
        if (has0) {
            float ia = g1_sm[aj      ][ab0];
            float fa = g1_sm[aj +  64][ab0];
            float ga = g1_sm[aj + 128][ab0];
            float oa = g1_sm[aj + 192][ab0];
            c1a = sigf(fa) * c1a + sigf(ia) * tanh_f(ga);
            h1_sm[ab0][aj] = sigf(oa) * tanh_f(c1a);
        }
        if (has1) {
            float ib = g1_sm[aj      ][ab1];
            float fb = g1_sm[aj +  64][ab1];
            float gb = g1_sm[aj + 128][ab1];
            float ob = g1_sm[aj + 192][ab1];
            c1b = sigf(fb) * c1b + sigf(ib) * tanh_f(gb);
            h1_sm[ab1][aj] = sigf(ob) * tanh_f(c1b);
        }
    }
    __syncthreads();       // final: h1 writes -> FC reads

    // ---------- FC: out[b][o] = b_fc[o] + sum_j h1_last[b][j] * w_fc[o][j] ----------
    if (tid < nb * NO) {
        int b = tid / NO, o = tid % NO;
        const float* wr = w_fc + o * Hh;
        const float* hr = &h1_sm[b][0];
        float s = b_fc[o];
        #pragma unroll
        for (int j = 0; j < Hh; j++) s += wr[j] * hr[j];
        out[(bbase + b) * NO + o] = s;
    }
}

extern "C" void kernel_launch(void* const* d_in, const int* in_sizes, int n_in,
                              void* d_out, int out_size) {
    (void)in_sizes; (void)n_in; (void)out_size;
    lstm_kernel<<<NCTA, NT>>>(
        (const float*)d_in[0],
        (const float*)d_in[1], (const float*)d_in[2],
        (const float*)d_in[3], (const float*)d_in[4],
        (const float*)d_in[5], (const float*)d_in[6],
        (const float*)d_in[7], (const float*)d_in[8],
        (const float*)d_in[9], (const float*)d_in[10],
        (float*)d_out);
}